// round 5
// baseline (speedup 1.0000x reference)
#include <cuda_runtime.h>
#include <math.h>
#include <stdint.h>

// ---------------- problem constants ----------------
#define BB 8
#define CC 512
#define LL 8192
#define KS 3
#define WELEMS (CC*CC*KS)

// ---------------- layout / tiling ----------------
#define XL 8448                 // padded rows per batch (8 front pad + 8192 + tail; pads stay zero)
#define XPAD 8
#define OT 64                   // block O tile
#define LT 128                  // block L tile
#define KC 64                   // ci per chunk (int8 -> 64B rows)
#define NCHUNK (CC/KC)          // 8
#define XROWS 138               // LT + 2*5 halo
#define PITCH 80                // smem row pitch bytes (64B data) -> conflict-free ldmatrix
#define W_OFF 0
#define W_BYTES (3*OT*PITCH)    // 15360
#define X_OFF W_BYTES
#define X_BYTES (2*XROWS*PITCH) // 22080
#define STAGE_BYTES 37504
#define NSEG_W (3*OT*4)         // 768
#define NSEG_X (2*XROWS*4)      // 1104
#define NSEG (NSEG_W + NSEG_X)  // 1872
#define SMEM_TOTAL (2*STAGE_BYTES)  // 75008
#define YPITCH 133

#define ACT_ELEMS ((size_t)BB*XL*CC)

// ---------------- device scratch (zero-initialized; pads stay zero) ----------------
__device__ __align__(1024) float g_y[ACT_ELEMS];                 // fp32 staging [b][l][c]
__device__ __align__(1024) signed char g_qx[2*ACT_ELEMS];        // x quantized, lvl-major
__device__ __align__(1024) signed char g_qh[2*ACT_ELEMS];        // h quantized
__device__ __align__(1024) signed char g_qw[(size_t)18*CC*CC];   // ternary weights [widx*3+tap][o][ci]
__device__ float g_partial[256];
__device__ float g_wscales[6];
__device__ unsigned g_amax_bits[8];   // slots: 0:x0, 1:h0, 2:x1, 3:h1, 4:x2, 5:h2, 6:x3

// ---------------- asm helpers ----------------
__device__ __forceinline__ uint32_t smem_u32(const void* p) {
    uint32_t a;
    asm("{ .reg .u64 t; cvta.to.shared.u64 t, %1; cvt.u32.u64 %0, t; }" : "=r"(a) : "l"(p));
    return a;
}
__device__ __forceinline__ void cp16(uint32_t saddr, const void* gaddr) {
    asm volatile("cp.async.cg.shared.global [%0], [%1], 16;" :: "r"(saddr), "l"(gaddr));
}
__device__ __forceinline__ void cp_commit() { asm volatile("cp.async.commit_group;"); }
template<int N> __device__ __forceinline__ void cp_wait() {
    asm volatile("cp.async.wait_group %0;" :: "n"(N));
}
__device__ __forceinline__ void ldm_x4(uint32_t* r, uint32_t addr) {
    asm volatile("ldmatrix.sync.aligned.m8n8.x4.shared.b16 {%0,%1,%2,%3}, [%4];"
                 : "=r"(r[0]), "=r"(r[1]), "=r"(r[2]), "=r"(r[3]) : "r"(addr));
}
__device__ __forceinline__ void mma16832(int* d, const uint32_t* a, const uint32_t* b0, const uint32_t* b1) {
    asm volatile("mma.sync.aligned.m16n8k32.row.col.s32.s8.s8.s32 "
                 "{%0,%1,%2,%3}, {%4,%5,%6,%7}, {%8,%9}, {%0,%1,%2,%3};"
                 : "+r"(d[0]), "+r"(d[1]), "+r"(d[2]), "+r"(d[3])
                 : "r"(a[0]), "r"(a[1]), "r"(a[2]), "r"(a[3]), "r"(*b0), "r"(*b1));
}

// ---------------- reset per-launch state ----------------
__global__ void reset_k() {
    if (threadIdx.x < 8) g_amax_bits[threadIdx.x] = 0u;
}

// ---------------- weight quantization ----------------
__global__ void absmean_partial_k(const float* __restrict__ w) {
    __shared__ float red[256];
    float s = 0.f;
    for (int i = blockIdx.x*256 + threadIdx.x; i < WELEMS; i += 256*256) s += fabsf(w[i]);
    red[threadIdx.x] = s;
    __syncthreads();
    for (int st = 128; st > 0; st >>= 1) {
        if (threadIdx.x < st) red[threadIdx.x] += red[threadIdx.x + st];
        __syncthreads();
    }
    if (threadIdx.x == 0) g_partial[blockIdx.x] = red[0];
}
__global__ void absmean_final_k(int widx) {
    __shared__ float red[256];
    red[threadIdx.x] = g_partial[threadIdx.x];
    __syncthreads();
    for (int st = 128; st > 0; st >>= 1) {
        if (threadIdx.x < st) red[threadIdx.x] += red[threadIdx.x + st];
        __syncthreads();
    }
    if (threadIdx.x == 0) g_wscales[widx] = red[0] / (float)WELEMS + 1e-5f;
}
// w [o][i][k] -> g_qw[(widx*3+k)][o][i] ternary int8 (exact; scale applied in epilogue)
__global__ void wquant_k(const float* __restrict__ w, int widx) {
    int idx = blockIdx.x*256 + threadIdx.x;
    if (idx >= WELEMS) return;
    float s = g_wscales[widx];
    int k = idx % KS;
    int i = (idx / KS) % CC;
    int o = idx / (KS*CC);
    float q = rintf(w[idx] / s);
    q = fminf(1.f, fmaxf(-1.f, q));
    g_qw[(((size_t)widx*3 + k)*CC + o)*CC + i] = (signed char)(int)q;
}

// ---------------- initial transpose fp32 [b][c][l] -> g_y [b][l][c] + amax[0] ----------------
__global__ void transpose_x_k(const float* __restrict__ src) {
    __shared__ float t[32][65];
    __shared__ float red[8];
    int b = blockIdx.z, c0 = blockIdx.y*32, l0 = blockIdx.x*64;
#pragma unroll
    for (int k = 0; k < 8; k++) {
        int idx = threadIdx.x + k*256;
        int cl = idx >> 6, ll_ = idx & 63;
        t[cl][ll_] = src[((size_t)b*CC + c0 + cl)*LL + l0 + ll_];
    }
    __syncthreads();
    float lm = 0.f;
#pragma unroll
    for (int k = 0; k < 8; k++) {
        int idx = threadIdx.x + k*256;
        int ll_ = idx >> 5, cl = idx & 31;
        float v = t[cl][ll_];
        g_y[((size_t)b*XL + XPAD + l0 + ll_)*CC + c0 + cl] = v;
        lm = fmaxf(lm, fabsf(v));
    }
#pragma unroll
    for (int s = 16; s > 0; s >>= 1) lm = fmaxf(lm, __shfl_xor_sync(0xffffffffu, lm, s));
    if ((threadIdx.x & 31) == 0) red[threadIdx.x >> 5] = lm;
    __syncthreads();
    if (threadIdx.x < 32) {
        lm = (threadIdx.x < 8) ? red[threadIdx.x] : 0.f;
#pragma unroll
        for (int s = 4; s > 0; s >>= 1) lm = fmaxf(lm, __shfl_xor_sync(0xffffffffu, lm, s));
        if (threadIdx.x == 0) atomicMax(&g_amax_bits[0], __float_as_uint(lm));
    }
}

// ---------------- activation quantization: g_y -> (q1, q2) int8 ----------------
__global__ void quant_act_k(signed char* __restrict__ dst, int slot) {
    size_t idx = (size_t)blockIdx.x*256 + threadIdx.x;   // 8388608 total
    float amax = __uint_as_float(g_amax_bits[slot]);
    float s1 = fmaxf(amax, 1e-30f) * (1.0f/127.0f);
    float inv1 = 1.0f/s1;
    float inv2 = 128.0f/s1;
    size_t gi = idx*4;
    int c = (int)(gi & 511);
    size_t rest = gi >> 9;
    int l = (int)(rest & 8191);
    int b = (int)(rest >> 13);
    size_t off = ((size_t)b*XL + XPAD + l)*CC + c;
    float4 v = *(const float4*)&g_y[off];
    int q10 = __float2int_rn(v.x*inv1), q11 = __float2int_rn(v.y*inv1);
    int q12 = __float2int_rn(v.z*inv1), q13 = __float2int_rn(v.w*inv1);
    float r0 = fmaf((float)-q10, s1, v.x), r1 = fmaf((float)-q11, s1, v.y);
    float r2 = fmaf((float)-q12, s1, v.z), r3 = fmaf((float)-q13, s1, v.w);
    int q20 = __float2int_rn(r0*inv2), q21 = __float2int_rn(r1*inv2);
    int q22 = __float2int_rn(r2*inv2), q23 = __float2int_rn(r3*inv2);
    uint32_t p1 = (q10&255) | ((q11&255)<<8) | ((q12&255)<<16) | ((uint32_t)(q13&255)<<24);
    uint32_t p2 = (q20&255) | ((q21&255)<<8) | ((q22&255)<<16) | ((uint32_t)(q23&255)<<24);
    *(uint32_t*)&dst[off] = p1;
    *(uint32_t*)&dst[ACT_ELEMS + off] = p2;
}

// ---------------- fused conv kernel (int8 mma implicit GEMM) ----------------
// D_lvl[o=64][l=128] = sum over ci(512), taps(3) of Q_tap[o][ci] * q_lvl[l+(tap-1)d][ci]
// y = wscale*s1*(D1 + D2/128) + bias
// mode 0: y=leakyrelu(y) -> g_y; mode 1: xio += y (fp32 [b][c][l]); result -> g_y. amax[out_slot] updated.
__global__ void __launch_bounds__(256, 2)
conv_mma_kernel(const signed char* __restrict__ qsrc,  // [2][b][XL][CC] lvl-major
                const signed char* __restrict__ qw,    // [3][CC][CC] for this layer
                const float* __restrict__ bias,
                float* __restrict__ xio,
                int in_slot, int out_slot, int widx, int dil, int mode)
{
    extern __shared__ char smem[];
    const uint32_t sbase = smem_u32(smem);

    const int tid  = threadIdx.x;
    const int lane = tid & 31;
    const int w    = tid >> 5;
    const int o_w  = (w >> 2) * 32;     // warp O offset (0/32)
    const int l_w  = (w & 3) * 32;      // warp L offset (0..96)
    const int o0   = blockIdx.x * OT;
    const int l0   = blockIdx.y * LT;
    const int b    = blockIdx.z;

    // ---- per-thread cp.async segment table (chunk-invariant; +64B per chunk) ----
    uint32_t soff[8]; const char* gp[8]; int nseg = 0;
#pragma unroll
    for (int i = 0; i < 8; i++) {
        int s = tid + i*256;
        if (s < NSEG) {
            nseg = i + 1;
            if (s < NSEG_W) {
                int row = s >> 2, sg = s & 3;
                int tap = row >> 6, rr = row & 63;
                soff[i] = W_OFF + (uint32_t)row*PITCH + sg*16;
                gp[i] = (const char*)(qw + ((size_t)tap*CC + o0 + rr)*CC) + sg*16;
            } else {
                int t2 = s - NSEG_W;
                int row = t2 >> 2, sg = t2 & 3;
                int lvl = row / XROWS, rr = row % XROWS;
                soff[i] = X_OFF + (uint32_t)row*PITCH + sg*16;
                gp[i] = (const char*)(qsrc + (size_t)lvl*ACT_ELEMS
                        + ((size_t)b*XL + XPAD + l0 - 5 + rr)*CC) + sg*16;
            }
        }
    }

    // ---- ldmatrix base addresses ----
    uint32_t a_base[2];
#pragma unroll
    for (int m = 0; m < 2; m++)
        a_base[m] = sbase + W_OFF
                  + (uint32_t)(o_w + m*16 + (lane & 7) + ((lane >> 3) & 1)*8)*PITCH
                  + (lane >> 4)*16;
    uint32_t b_base[2];
#pragma unroll
    for (int p = 0; p < 2; p++)
        b_base[p] = sbase + X_OFF
                  + (uint32_t)(l_w + p*16 + (lane & 7) + ((lane >> 4) & 1)*8)*PITCH
                  + ((lane >> 3) & 1)*16;

    int acc1[2][4][4], acc2[2][4][4];
#pragma unroll
    for (int m = 0; m < 2; m++)
#pragma unroll
        for (int n = 0; n < 4; n++)
#pragma unroll
            for (int e = 0; e < 4; e++) { acc1[m][n][e] = 0; acc2[m][n][e] = 0; }

    const int Sx[3] = {5 - dil, 5, 5 + dil};

    // ---- prologue: issue chunks 0 and 1 ----
#pragma unroll
    for (int i = 0; i < 8; i++) if (i < nseg) cp16(sbase + soff[i], gp[i]);
    cp_commit();
#pragma unroll
    for (int i = 0; i < 8; i++) if (i < nseg) cp16(sbase + STAGE_BYTES + soff[i], gp[i] + KC);
    cp_commit();

    for (int c = 0; c < NCHUNK; c++) {
        if (c < NCHUNK - 2) cp_wait<1>(); else cp_wait<0>();
        __syncthreads();
        const uint32_t stg = (uint32_t)(c & 1) * STAGE_BYTES;
#pragma unroll
        for (int kp = 0; kp < 2; kp++) {
#pragma unroll
            for (int tap = 0; tap < 3; tap++) {
                uint32_t af[2][4];
#pragma unroll
                for (int m = 0; m < 2; m++)
                    ldm_x4(af[m], a_base[m] + stg + (uint32_t)tap*(OT*PITCH) + kp*32);
#pragma unroll
                for (int lvl = 0; lvl < 2; lvl++) {
                    const uint32_t boff = stg + (uint32_t)(lvl*XROWS + Sx[tap])*PITCH + kp*32;
                    uint32_t bf[2][4];
#pragma unroll
                    for (int p = 0; p < 2; p++) ldm_x4(bf[p], b_base[p] + boff);
#pragma unroll
                    for (int m = 0; m < 2; m++)
#pragma unroll
                        for (int p = 0; p < 2; p++) {
                            if (lvl == 0) {
                                mma16832(acc1[m][p*2],   af[m], &bf[p][0], &bf[p][1]);
                                mma16832(acc1[m][p*2+1], af[m], &bf[p][2], &bf[p][3]);
                            } else {
                                mma16832(acc2[m][p*2],   af[m], &bf[p][0], &bf[p][1]);
                                mma16832(acc2[m][p*2+1], af[m], &bf[p][2], &bf[p][3]);
                            }
                        }
                }
            }
        }
        __syncthreads();
        if (c + 2 < NCHUNK) {
            const int adv = (c + 2) * KC;
#pragma unroll
            for (int i = 0; i < 8; i++)
                if (i < nseg) cp16(sbase + stg + soff[i], gp[i] + adv);
            cp_commit();
        }
    }

    // ---- epilogue ----
    __shared__ float red8[8];
    float* yt = (float*)smem;
    const float amax_in = __uint_as_float(g_amax_bits[in_slot]);
    const float ws  = g_wscales[widx] * (amax_in * (1.0f/127.0f));
    const float ws2 = ws * (1.0f/128.0f);
    const int g  = lane >> 2;
    const int tg = lane & 3;
#pragma unroll
    for (int m = 0; m < 2; m++) {
        const int r0 = o_w + m*16 + g;
        const float bv0 = bias[o0 + r0];
        const float bv8 = bias[o0 + r0 + 8];
#pragma unroll
        for (int n = 0; n < 4; n++) {
            const int col = l_w + n*8 + tg*2;
            float y0 = ws*(float)acc1[m][n][0] + ws2*(float)acc2[m][n][0] + bv0;
            float y1 = ws*(float)acc1[m][n][1] + ws2*(float)acc2[m][n][1] + bv0;
            float y2 = ws*(float)acc1[m][n][2] + ws2*(float)acc2[m][n][2] + bv8;
            float y3 = ws*(float)acc1[m][n][3] + ws2*(float)acc2[m][n][3] + bv8;
            if (mode == 0) {
                y0 = (y0 >= 0.f) ? y0 : 0.1f*y0;
                y1 = (y1 >= 0.f) ? y1 : 0.1f*y1;
                y2 = (y2 >= 0.f) ? y2 : 0.1f*y2;
                y3 = (y3 >= 0.f) ? y3 : 0.1f*y3;
            }
            yt[r0*YPITCH + col]         = y0;
            yt[r0*YPITCH + col + 1]     = y1;
            yt[(r0+8)*YPITCH + col]     = y2;
            yt[(r0+8)*YPITCH + col + 1] = y3;
        }
    }
    __syncthreads();

    if (mode == 1) {
        for (int r = w; r < OT; r += 8) {
            float* rowp = xio + ((size_t)b*CC + o0 + r)*LL + l0;
#pragma unroll
            for (int i = 0; i < LT/32; i++) {
                int li = i*32 + lane;
                float xn = rowp[li] + yt[r*YPITCH + li];
                rowp[li] = xn;
                yt[r*YPITCH + li] = xn;
            }
        }
        __syncthreads();
    }

    // transposed fp32 store to g_y [b][l][c] + amax
    float lm = 0.f;
    const size_t lrow0 = ((size_t)b*XL + XPAD + l0)*CC + o0;
    for (int li = w; li < LT; li += 8) {
        float v0 = yt[lane*YPITCH + li];
        float v1 = yt[(lane+32)*YPITCH + li];
        size_t off = lrow0 + (size_t)li*CC + lane;
        g_y[off]      = v0;
        g_y[off + 32] = v1;
        lm = fmaxf(lm, fmaxf(fabsf(v0), fabsf(v1)));
    }
#pragma unroll
    for (int s = 16; s > 0; s >>= 1) lm = fmaxf(lm, __shfl_xor_sync(0xffffffffu, lm, s));
    if (lane == 0) red8[w] = lm;
    __syncthreads();
    if (tid < 32) {
        lm = (lane < 8) ? red8[lane] : 0.f;
#pragma unroll
        for (int s = 4; s > 0; s >>= 1) lm = fmaxf(lm, __shfl_xor_sync(0xffffffffu, lm, s));
        if (lane == 0) atomicMax(&g_amax_bits[out_slot], __float_as_uint(lm));
    }
}

// ---------------- host ----------------
extern "C" void kernel_launch(void* const* d_in, const int* in_sizes, int n_in,
                              void* d_out, int out_size) {
    const float* x = (const float*)d_in[0];
    float* out = (float*)d_out;

    void *qxp, *qhp, *qwp;
    cudaGetSymbolAddress(&qxp, g_qx);
    cudaGetSymbolAddress(&qhp, g_qh);
    cudaGetSymbolAddress(&qwp, g_qw);
    signed char* qx = (signed char*)qxp;
    signed char* qh = (signed char*)qhp;
    signed char* qw = (signed char*)qwp;

    static int smem_set = 0;
    if (!smem_set) {
        cudaFuncSetAttribute(conv_mma_kernel, cudaFuncAttributeMaxDynamicSharedMemorySize, SMEM_TOTAL);
        smem_set = 1;
    }

    reset_k<<<1, 32>>>();

    // Seed running x into d_out
    cudaMemcpyAsync(out, x, sizeof(float)*(size_t)BB*CC*LL, cudaMemcpyDeviceToDevice, 0);

    // Transpose x -> g_y [b][l][c] + amax[0]
    transpose_x_k<<<dim3(LL/64, CC/32, BB), 256>>>(x);

    // Quantize all 6 weight tensors (w at d_in 1,3,5,7,9,11)
    for (int t = 0; t < 6; t++) {
        const float* wt = (const float*)d_in[1 + 2*t];
        absmean_partial_k<<<256, 256>>>(wt);
        absmean_final_k<<<1, 256>>>(t);
        wquant_k<<<(WELEMS + 255)/256, 256>>>(wt, t);
    }

    // Quantize x0
    quant_act_k<<<32768, 256>>>(qx, 0);

    dim3 grid(CC/OT, LL/LT, BB);   // (8, 64, 8)
    const int dils[3] = {1, 3, 5};
    for (int br = 0; br < 3; br++) {
        const float* bA = (const float*)d_in[2 + 4*br];
        const float* bB = (const float*)d_in[4 + 4*br];
        // h = leakyrelu(convA_dilated(x)): qx -> g_y, amax[2br+1]
        conv_mma_kernel<<<grid, 256, SMEM_TOTAL>>>(
            qx, qw + (size_t)(2*br)*3*CC*CC, bA, out, 2*br, 2*br + 1, 2*br, dils[br], 0);
        quant_act_k<<<32768, 256>>>(qh, 2*br + 1);
        // x += convB_dense(h): qh -> d_out residual + g_y, amax[2br+2]
        conv_mma_kernel<<<grid, 256, SMEM_TOTAL>>>(
            qh, qw + (size_t)(2*br + 1)*3*CC*CC, bB, out, 2*br + 1, 2*br + 2, 2*br + 1, 1, 1);
        if (br < 2) quant_act_k<<<32768, 256>>>(qx, 2*br + 2);
    }
}

// round 12
// speedup vs baseline: 3.6146x; 3.6146x over previous
#include <cuda_runtime.h>
#include <cuda_fp16.h>
#include <math.h>
#include <stdint.h>

// ---------------- problem constants ----------------
#define BB 8
#define CC 512
#define LL 8192
#define KS 3
#define WELEMS (CC*CC*KS)

// ---------------- layout / tiling ----------------
#define XL 8448                 // padded rows per batch: 8 front pad + 8192 + tail pad (zeros)
#define XPAD 8
#define OT 64                   // block O tile
#define LT 128                  // block L tile
#define KC 32                   // ci per chunk
#define NCHUNK (CC/KC)          // 16
#define XROWS 138               // LT + 2*5 halo
#define PITCH 80                // smem row pitch bytes (64B data) -> conflict-free ldmatrix
#define W_OFF 0
#define W_BYTES (3*OT*PITCH)    // 15360
#define X_OFF W_BYTES
#define X_BYTES (XROWS*PITCH)   // 11040
#define STAGE_BYTES 26496       // aligned(W_BYTES + X_BYTES, 128)
#define NSEG_W (3*OT*4)         // 768 16B segments
#define NSEG_X (XROWS*4)        // 552
#define NSEG (NSEG_W + NSEG_X)  // 1320
#define MAXSEG 6                // ceil(1320/256)
#define SMEM_TOTAL (2*STAGE_BYTES)  // 52992 (epilogue yt reuses stage0)
#define YPITCH 133              // fp32 epilogue pitch (conflict-free columns)

// ---------------- device scratch (zero-initialized; pads stay zero) ----------------
__device__ __align__(1024) __half g_xt[(size_t)BB*XL*CC];       // x fp16 [b][l][c]
__device__ __align__(1024) __half g_ht[(size_t)BB*XL*CC];       // h fp16 [b][l][c]
__device__ __align__(1024) __half g_q[(size_t)18*CC*CC];        // ternary weights [widx*3+tap][o][ci]
__device__ float g_partial[256];
__device__ float g_scales[6];

// ---------------- asm helpers ----------------
__device__ __forceinline__ uint32_t smem_u32(const void* p) {
    uint32_t a;
    asm("{ .reg .u64 t; cvta.to.shared.u64 t, %1; cvt.u32.u64 %0, t; }" : "=r"(a) : "l"(p));
    return a;
}
__device__ __forceinline__ void cp16(uint32_t saddr, const void* gaddr) {
    asm volatile("cp.async.cg.shared.global [%0], [%1], 16;" :: "r"(saddr), "l"(gaddr));
}
__device__ __forceinline__ void cp_commit() { asm volatile("cp.async.commit_group;"); }
template<int N> __device__ __forceinline__ void cp_wait() {
    asm volatile("cp.async.wait_group %0;" :: "n"(N));
}
__device__ __forceinline__ void ldm_x4(uint32_t* r, uint32_t addr) {
    asm volatile("ldmatrix.sync.aligned.m8n8.x4.shared.b16 {%0,%1,%2,%3}, [%4];"
                 : "=r"(r[0]), "=r"(r[1]), "=r"(r[2]), "=r"(r[3]) : "r"(addr));
}
__device__ __forceinline__ void ldm_x2(uint32_t* r, uint32_t addr) {
    asm volatile("ldmatrix.sync.aligned.m8n8.x2.shared.b16 {%0,%1}, [%2];"
                 : "=r"(r[0]), "=r"(r[1]) : "r"(addr));
}
__device__ __forceinline__ void mma16816(float* d, const uint32_t* a, const uint32_t* b) {
    asm volatile("mma.sync.aligned.m16n8k16.row.col.f32.f16.f16.f32 "
                 "{%0,%1,%2,%3}, {%4,%5,%6,%7}, {%8,%9}, {%0,%1,%2,%3};"
                 : "+f"(d[0]), "+f"(d[1]), "+f"(d[2]), "+f"(d[3])
                 : "r"(a[0]), "r"(a[1]), "r"(a[2]), "r"(a[3]), "r"(b[0]), "r"(b[1]));
}

// ---------------- weight quantization ----------------
__global__ void absmean_partial_k(const float* __restrict__ w) {
    __shared__ float red[256];
    float s = 0.f;
    for (int i = blockIdx.x*256 + threadIdx.x; i < WELEMS; i += 256*256) s += fabsf(w[i]);
    red[threadIdx.x] = s;
    __syncthreads();
    for (int st = 128; st > 0; st >>= 1) {
        if (threadIdx.x < st) red[threadIdx.x] += red[threadIdx.x + st];
        __syncthreads();
    }
    if (threadIdx.x == 0) g_partial[blockIdx.x] = red[0];
}
__global__ void absmean_final_k(int widx) {
    __shared__ float red[256];
    red[threadIdx.x] = g_partial[threadIdx.x];
    __syncthreads();
    for (int st = 128; st > 0; st >>= 1) {
        if (threadIdx.x < st) red[threadIdx.x] += red[threadIdx.x + st];
        __syncthreads();
    }
    if (threadIdx.x == 0) g_scales[widx] = red[0] / (float)WELEMS + 1e-5f;
}
// src w [o][i][k] -> g_q[(widx*3+k)][o][i] ternary fp16 (exact; scale applied in epilogue)
__global__ void quantize_k(const float* __restrict__ w, int widx) {
    int idx = blockIdx.x*256 + threadIdx.x;
    if (idx >= WELEMS) return;
    float s = g_scales[widx];
    int k = idx % KS;
    int i = (idx / KS) % CC;
    int o = idx / (KS*CC);
    float q = rintf(w[idx] / s);
    q = fminf(1.f, fmaxf(-1.f, q));
    g_q[(((size_t)widx*3 + k)*CC + o)*CC + i] = __float2half_rn(q);
}

// ---------------- initial transpose: fp32 [b][c][l] -> fp16 [b][l][c] ----------------
__global__ void transpose_split_k(const float* __restrict__ src) {
    __shared__ float t[32][65];
    int b = blockIdx.z, c0 = blockIdx.y*32, l0 = blockIdx.x*64;
#pragma unroll
    for (int k = 0; k < 8; k++) {
        int idx = threadIdx.x + k*256;
        int cl = idx >> 6, ll_ = idx & 63;
        t[cl][ll_] = src[((size_t)b*CC + c0 + cl)*LL + l0 + ll_];
    }
    __syncthreads();
#pragma unroll
    for (int k = 0; k < 8; k++) {
        int idx = threadIdx.x + k*256;
        int ll_ = idx >> 5, cl = idx & 31;
        g_xt[((size_t)b*XL + XPAD + l0 + ll_)*CC + c0 + cl] = __float2half_rn(t[cl][ll_]);
    }
}

// ---------------- fused conv kernel (fp16 mma.sync implicit GEMM) ----------------
// D[o=64][l=128] = sum over ci(512), taps(3) of Q_tap[o][ci] * X[l+(tap-1)d][ci]
// mode 0: out = leakyrelu(s*D + bias) -> fp16 [b][l][c]
// mode 1: xio += s*D + bias (fp32 [b][c][l]); new x -> fp16 [b][l][c]
__global__ void __launch_bounds__(256, 2)
conv_mma_kernel(const __half* __restrict__ Wq,   // [3][512][512] for this layer
                const __half* __restrict__ Xt,   // [b][XL][512]
                const float* __restrict__ bias,
                float* __restrict__ xio,
                __half* __restrict__ out_t,
                int widx, int dil, int mode)
{
    extern __shared__ char smem[];
    const uint32_t sbase = smem_u32(smem);

    const int tid  = threadIdx.x;
    const int lane = tid & 31;
    const int w    = tid >> 5;
    const int o_w  = (w >> 2) * 32;     // warp O offset (0/32)
    const int l_w  = (w & 3) * 32;      // warp L offset (0..96)
    const int o0   = blockIdx.x * OT;
    const int l0   = blockIdx.y * LT;
    const int b    = blockIdx.z;

    // ---- per-thread cp.async segment table (chunk-invariant; +64B per chunk) ----
    uint32_t soff[MAXSEG]; const char* gp[MAXSEG]; int nseg = 0;
#pragma unroll
    for (int i = 0; i < MAXSEG; i++) {
        int s = tid + i*256;
        if (s < NSEG) {
            nseg = i + 1;
            if (s < NSEG_W) {
                int tap = s >> 8, rr = (s & 255) >> 2, sg = s & 3;
                soff[i] = W_OFF + (uint32_t)(tap*OT + rr)*PITCH + sg*16;
                gp[i] = (const char*)(Wq + ((size_t)tap*CC + o0 + rr)*CC) + sg*16;
            } else {
                int t2 = s - NSEG_W;
                int rr = t2 >> 2, sg = t2 & 3;
                soff[i] = X_OFF + (uint32_t)rr*PITCH + sg*16;
                gp[i] = (const char*)(Xt + ((size_t)b*XL + XPAD + l0 - 5 + rr)*CC) + sg*16;
            }
        }
    }

    // ---- ldmatrix base addresses ----
    // A (W, row-major [o][ci]): x4 mats: (r0-7,k0),(r8-15,k0),(r0-7,k+16B),(r8-15,k+16B)
    uint32_t a_base[2];
#pragma unroll
    for (int m = 0; m < 2; m++)
        a_base[m] = sbase + W_OFF
                  + (uint32_t)(o_w + m*16 + (lane & 7) + ((lane >> 3) & 1)*8)*PITCH
                  + (lane >> 4)*16;
    // B (X, [l][ci] k-contig): x2 mats: (n0-7,k0),(n0-7,k+16B); lanes 0-15 drive addresses
    uint32_t b_base[4];
#pragma unroll
    for (int n = 0; n < 4; n++)
        b_base[n] = sbase + X_OFF
                  + (uint32_t)(l_w + n*8 + (lane & 7))*PITCH
                  + ((lane >> 3) & 1)*16;

    float acc[2][4][4];
#pragma unroll
    for (int m = 0; m < 2; m++)
#pragma unroll
        for (int n = 0; n < 4; n++)
#pragma unroll
            for (int e = 0; e < 4; e++) acc[m][n][e] = 0.f;

    const int Sx[3] = {5 - dil, 5, 5 + dil};

    // ---- prologue: issue chunks 0 and 1 ----
#pragma unroll
    for (int i = 0; i < MAXSEG; i++) if (i < nseg) cp16(sbase + soff[i], gp[i]);
    cp_commit();
#pragma unroll
    for (int i = 0; i < MAXSEG; i++) if (i < nseg) cp16(sbase + STAGE_BYTES + soff[i], gp[i] + 64);
    cp_commit();

    for (int c = 0; c < NCHUNK; c++) {
        if (c < NCHUNK - 2) cp_wait<1>(); else cp_wait<0>();
        __syncthreads();
        const uint32_t stg = (uint32_t)(c & 1) * STAGE_BYTES;
#pragma unroll
        for (int k16 = 0; k16 < 2; k16++) {
#pragma unroll
            for (int tap = 0; tap < 3; tap++) {
                uint32_t afrag[2][4];
#pragma unroll
                for (int m = 0; m < 2; m++)
                    ldm_x4(afrag[m], a_base[m] + stg + (uint32_t)tap*(OT*PITCH) + k16*32);
                uint32_t bfrag[4][2];
                const uint32_t boff = stg + (uint32_t)Sx[tap]*PITCH + k16*32;
#pragma unroll
                for (int n = 0; n < 4; n++) ldm_x2(bfrag[n], b_base[n] + boff);
#pragma unroll
                for (int m = 0; m < 2; m++)
#pragma unroll
                    for (int n = 0; n < 4; n++)
                        mma16816(acc[m][n], afrag[m], bfrag[n]);
            }
        }
        __syncthreads();
        if (c + 2 < NCHUNK) {
            const int adv = (c + 2) * 64;
#pragma unroll
            for (int i = 0; i < MAXSEG; i++)
                if (i < nseg) cp16(sbase + stg + soff[i], gp[i] + adv);
            cp_commit();
        }
    }

    // ---- epilogue: stage y = s*acc + bias (leaky if mode 0) into smem [o][l] ----
    float* yt = (float*)smem;                 // reuses pipeline smem; pitch YPITCH
    const float s = g_scales[widx];
    const int g  = lane >> 2;
    const int tg = lane & 3;
#pragma unroll
    for (int m = 0; m < 2; m++) {
        const int r0 = o_w + m*16 + g;
        const float bv0 = bias[o0 + r0];
        const float bv8 = bias[o0 + r0 + 8];
#pragma unroll
        for (int n = 0; n < 4; n++) {
            const int col = l_w + n*8 + tg*2;
            float y0 = fmaf(s, acc[m][n][0], bv0);
            float y1 = fmaf(s, acc[m][n][1], bv0);
            float y2 = fmaf(s, acc[m][n][2], bv8);
            float y3 = fmaf(s, acc[m][n][3], bv8);
            if (mode == 0) {
                y0 = (y0 >= 0.f) ? y0 : 0.1f*y0;
                y1 = (y1 >= 0.f) ? y1 : 0.1f*y1;
                y2 = (y2 >= 0.f) ? y2 : 0.1f*y2;
                y3 = (y3 >= 0.f) ? y3 : 0.1f*y3;
            }
            yt[r0*YPITCH + col]         = y0;
            yt[r0*YPITCH + col + 1]     = y1;
            yt[(r0+8)*YPITCH + col]     = y2;
            yt[(r0+8)*YPITCH + col + 1] = y3;
        }
    }
    __syncthreads();

    if (mode == 1) {
        // residual add on fp32 x [b][c][l], coalesced over l; update yt in place
        for (int r = w; r < OT; r += 8) {
            float* rowp = xio + ((size_t)b*CC + o0 + r)*LL + l0;
#pragma unroll
            for (int i = 0; i < LT/32; i++) {
                int li = i*32 + lane;
                float xn = rowp[li] + yt[r*YPITCH + li];
                rowp[li] = xn;
                yt[r*YPITCH + li] = xn;
            }
        }
        __syncthreads();
    }

    // transposed fp16 store: [b][l][c], coalesced over c
    const size_t lrow0 = ((size_t)b*XL + XPAD + l0)*CC + o0;
    for (int li = w; li < LT; li += 8) {
        float v0 = yt[lane*YPITCH + li];
        float v1 = yt[(lane+32)*YPITCH + li];
        size_t off = lrow0 + (size_t)li*CC + lane;
        out_t[off]      = __float2half_rn(v0);
        out_t[off + 32] = __float2half_rn(v1);
    }
}

// ---------------- host ----------------
extern "C" void kernel_launch(void* const* d_in, const int* in_sizes, int n_in,
                              void* d_out, int out_size) {
    const float* x = (const float*)d_in[0];
    float* out = (float*)d_out;

    void *qp, *xp, *hp;
    cudaGetSymbolAddress(&qp, g_q);
    cudaGetSymbolAddress(&xp, g_xt);
    cudaGetSymbolAddress(&hp, g_ht);
    __half* qb = (__half*)qp;
    __half* xb = (__half*)xp;
    __half* hb = (__half*)hp;

    static int smem_set = 0;
    if (!smem_set) {
        cudaFuncSetAttribute(conv_mma_kernel, cudaFuncAttributeMaxDynamicSharedMemorySize, SMEM_TOTAL);
        smem_set = 1;
    }

    // Seed running x into d_out
    cudaMemcpyAsync(out, x, sizeof(float)*(size_t)BB*CC*LL, cudaMemcpyDeviceToDevice, 0);

    // Initial transpose of x -> fp16 [b][l][c]
    transpose_split_k<<<dim3(LL/64, CC/32, BB), 256>>>(x);

    // Quantize all 6 weight tensors (w at d_in 1,3,5,7,9,11)
    for (int t = 0; t < 6; t++) {
        const float* wt = (const float*)d_in[1 + 2*t];
        absmean_partial_k<<<256, 256>>>(wt);
        absmean_final_k<<<1, 256>>>(t);
        quantize_k<<<(WELEMS + 255)/256, 256>>>(wt, t);
    }

    dim3 grid(CC/OT, LL/LT, BB);   // (8, 64, 8) — o fastest so same-X blocks are adjacent
    const int dils[3] = {1, 3, 5};
    for (int br = 0; br < 3; br++) {
        const float* bA = (const float*)d_in[2 + 4*br];
        const float* bB = (const float*)d_in[4 + 4*br];
        // h = leakyrelu(convA_dilated(x)) -> ht
        conv_mma_kernel<<<grid, 256, SMEM_TOTAL>>>(
            qb + (size_t)(2*br)*3*CC*CC, xb, bA, out, hb, 2*br, dils[br], 0);
        // x += convB_dense(h); new x -> xt
        conv_mma_kernel<<<grid, 256, SMEM_TOTAL>>>(
            qb + (size_t)(2*br+1)*3*CC*CC, hb, bB, out, xb, 2*br+1, 1, 1);
    }
}

// round 13
// speedup vs baseline: 4.0458x; 1.1193x over previous
#include <cuda_runtime.h>
#include <cuda_fp16.h>
#include <math.h>
#include <stdint.h>

// ---------------- problem constants ----------------
#define BB 8
#define CC 512
#define LL 8192
#define KS 3
#define WELEMS (CC*CC*KS)

// ---------------- layout / tiling ----------------
#define XL 8448                 // padded rows per batch: 8 front pad + 8192 + tail pad (zeros)
#define XPAD 8
#define OT 128                  // block O tile
#define LT 256                  // block L tile
#define KC 32                   // ci per chunk
#define NCHUNK (CC/KC)          // 16
#define XROWS 266               // LT + 2*5 halo
#define PITCH 80                // smem row pitch bytes (64B data) -> conflict-free ldmatrix
#define W_OFF 0
#define W_BYTES (3*OT*PITCH)    // 30720
#define X_OFF W_BYTES
#define X_BYTES (XROWS*PITCH)   // 21280
#define STAGE_BYTES 52096       // aligned(W_BYTES + X_BYTES, 128)
#define NSEG_W (3*OT*4)         // 1536 16B segments
#define NSEG_X (XROWS*4)        // 1064
#define NSEG (NSEG_W + NSEG_X)  // 2600
#define YPITCH 261              // fp32 epilogue pitch (261%32=5, gcd(5,32)=1 -> conflict-free cols)
#define SMEM_TOTAL 133632       // max(2*STAGE_BYTES=104192, OT*YPITCH*4=133632)

// ---------------- device scratch (zero-initialized; pads stay zero) ----------------
__device__ __align__(1024) __half g_xt[(size_t)BB*XL*CC];       // x fp16 [b][l][c]
__device__ __align__(1024) __half g_ht[(size_t)BB*XL*CC];       // h fp16 [b][l][c]
__device__ __align__(1024) __half g_q[(size_t)18*CC*CC];        // ternary weights [widx*3+tap][o][ci]
__device__ float g_partial[256];
__device__ float g_scales[6];

// ---------------- asm helpers ----------------
__device__ __forceinline__ uint32_t smem_u32(const void* p) {
    uint32_t a;
    asm("{ .reg .u64 t; cvta.to.shared.u64 t, %1; cvt.u32.u64 %0, t; }" : "=r"(a) : "l"(p));
    return a;
}
__device__ __forceinline__ void cp16(uint32_t saddr, const void* gaddr) {
    asm volatile("cp.async.cg.shared.global [%0], [%1], 16;" :: "r"(saddr), "l"(gaddr));
}
__device__ __forceinline__ void cp_commit() { asm volatile("cp.async.commit_group;"); }
template<int N> __device__ __forceinline__ void cp_wait() {
    asm volatile("cp.async.wait_group %0;" :: "n"(N));
}
__device__ __forceinline__ void ldm_x4(uint32_t* r, uint32_t addr) {
    asm volatile("ldmatrix.sync.aligned.m8n8.x4.shared.b16 {%0,%1,%2,%3}, [%4];"
                 : "=r"(r[0]), "=r"(r[1]), "=r"(r[2]), "=r"(r[3]) : "r"(addr));
}
__device__ __forceinline__ void ldm_x2(uint32_t* r, uint32_t addr) {
    asm volatile("ldmatrix.sync.aligned.m8n8.x2.shared.b16 {%0,%1}, [%2];"
                 : "=r"(r[0]), "=r"(r[1]) : "r"(addr));
}
__device__ __forceinline__ void mma16816(float* d, const uint32_t* a, const uint32_t* b) {
    asm volatile("mma.sync.aligned.m16n8k16.row.col.f32.f16.f16.f32 "
                 "{%0,%1,%2,%3}, {%4,%5,%6,%7}, {%8,%9}, {%0,%1,%2,%3};"
                 : "+f"(d[0]), "+f"(d[1]), "+f"(d[2]), "+f"(d[3])
                 : "r"(a[0]), "r"(a[1]), "r"(a[2]), "r"(a[3]), "r"(b[0]), "r"(b[1]));
}

// ---------------- weight quantization ----------------
__global__ void absmean_partial_k(const float* __restrict__ w) {
    __shared__ float red[256];
    float s = 0.f;
    for (int i = blockIdx.x*256 + threadIdx.x; i < WELEMS; i += 256*256) s += fabsf(w[i]);
    red[threadIdx.x] = s;
    __syncthreads();
    for (int st = 128; st > 0; st >>= 1) {
        if (threadIdx.x < st) red[threadIdx.x] += red[threadIdx.x + st];
        __syncthreads();
    }
    if (threadIdx.x == 0) g_partial[blockIdx.x] = red[0];
}
__global__ void absmean_final_k(int widx) {
    __shared__ float red[256];
    red[threadIdx.x] = g_partial[threadIdx.x];
    __syncthreads();
    for (int st = 128; st > 0; st >>= 1) {
        if (threadIdx.x < st) red[threadIdx.x] += red[threadIdx.x + st];
        __syncthreads();
    }
    if (threadIdx.x == 0) g_scales[widx] = red[0] / (float)WELEMS + 1e-5f;
}
// src w [o][i][k] -> g_q[(widx*3+k)][o][i] ternary fp16 (exact; scale applied in epilogue)
__global__ void quantize_k(const float* __restrict__ w, int widx) {
    int idx = blockIdx.x*256 + threadIdx.x;
    if (idx >= WELEMS) return;
    float s = g_scales[widx];
    int k = idx % KS;
    int i = (idx / KS) % CC;
    int o = idx / (KS*CC);
    float q = rintf(w[idx] / s);
    q = fminf(1.f, fmaxf(-1.f, q));
    g_q[(((size_t)widx*3 + k)*CC + o)*CC + i] = __float2half_rn(q);
}

// ---------------- initial transpose: fp32 [b][c][l] -> fp16 [b][l][c] ----------------
__global__ void transpose_split_k(const float* __restrict__ src) {
    __shared__ float t[32][65];
    int b = blockIdx.z, c0 = blockIdx.y*32, l0 = blockIdx.x*64;
#pragma unroll
    for (int k = 0; k < 8; k++) {
        int idx = threadIdx.x + k*256;
        int cl = idx >> 6, ll_ = idx & 63;
        t[cl][ll_] = src[((size_t)b*CC + c0 + cl)*LL + l0 + ll_];
    }
    __syncthreads();
#pragma unroll
    for (int k = 0; k < 8; k++) {
        int idx = threadIdx.x + k*256;
        int ll_ = idx >> 5, cl = idx & 31;
        g_xt[((size_t)b*XL + XPAD + l0 + ll_)*CC + c0 + cl] = __float2half_rn(t[cl][ll_]);
    }
}

// ---------------- staging: one chunk's W+X -> smem stage (on-the-fly addressing) ----------------
__device__ __forceinline__ void stage_chunk(uint32_t sdst, const __half* Wq, const __half* Xt,
                                            int o0, size_t xrowbase, int tid, int adv) {
    for (int s = tid; s < NSEG; s += 256) {
        uint32_t so; const char* g;
        if (s < NSEG_W) {
            int row = s >> 2, sg = s & 3;           // row in [0,384)
            int tap = row >> 7, rr = row & 127;     // OT=128 -> shifts
            so = W_OFF + (uint32_t)row*PITCH + sg*16;
            g = (const char*)(Wq + ((size_t)tap*CC + o0 + rr)*CC) + sg*16 + adv;
        } else {
            int t2 = s - NSEG_W;
            int row = t2 >> 2, sg = t2 & 3;
            so = X_OFF + (uint32_t)row*PITCH + sg*16;
            g = (const char*)(Xt + (xrowbase + row)*CC) + sg*16 + adv;
        }
        cp16(sdst + so, g);
    }
    cp_commit();
}

// ---------------- fused conv kernel (fp16 mma.sync implicit GEMM) ----------------
// block tile 128(O) x 256(L); 8 warps as 2(O) x 4(L); warp tile 64x64 (m=4, n=8)
// D[o][l] = sum over ci(512), taps(3) of Q_tap[o][ci] * X[l+(tap-1)d][ci]
// mode 0: out = leakyrelu(s*D + bias) -> fp16 [b][l][c]
// mode 1: xio += s*D + bias (fp32 [b][c][l]); new x -> fp16 [b][l][c]
__global__ void __launch_bounds__(256, 1)
conv_mma_kernel(const __half* __restrict__ Wq,   // [3][512][512] for this layer
                const __half* __restrict__ Xt,   // [b][XL][512]
                const float* __restrict__ bias,
                float* __restrict__ xio,
                __half* __restrict__ out_t,
                int widx, int dil, int mode)
{
    extern __shared__ char smem[];
    const uint32_t sbase = smem_u32(smem);

    const int tid  = threadIdx.x;
    const int lane = tid & 31;
    const int w    = tid >> 5;
    const int o_w  = (w >> 2) * 64;     // warp O offset (0/64)
    const int l_w  = (w & 3) * 64;      // warp L offset (0..192)
    const int o0   = blockIdx.x * OT;
    const int l0   = blockIdx.y * LT;
    const int b    = blockIdx.z;
    const size_t xrowbase = (size_t)b*XL + XPAD + l0 - 5;

    // ---- ldmatrix base addresses ----
    // A (W, row-major [o][ci]): per (k16,tap,m): ldm_x4 of 16x16
    const uint32_t a_base = sbase + W_OFF
                  + (uint32_t)(o_w + (lane & 7) + ((lane >> 3) & 1)*8)*PITCH
                  + (lane >> 4)*16;
    // B (X, [l][ci] k-contig): per (k16,tap,n): ldm_x2 of 8 l-rows x 16 ci
    const uint32_t b_base = sbase + X_OFF
                  + (uint32_t)(l_w + (lane & 7))*PITCH
                  + ((lane >> 3) & 1)*16;

    float acc[4][8][4];
#pragma unroll
    for (int m = 0; m < 4; m++)
#pragma unroll
        for (int n = 0; n < 8; n++)
#pragma unroll
            for (int e = 0; e < 4; e++) acc[m][n][e] = 0.f;

    const int Sx[3] = {5 - dil, 5, 5 + dil};

    // ---- prologue: issue chunks 0 and 1 ----
    stage_chunk(sbase,               Wq, Xt, o0, xrowbase, tid, 0);
    stage_chunk(sbase + STAGE_BYTES, Wq, Xt, o0, xrowbase, tid, 64);

    for (int c = 0; c < NCHUNK; c++) {
        if (c < NCHUNK - 2) cp_wait<1>(); else cp_wait<0>();
        __syncthreads();
        const uint32_t stg = (uint32_t)(c & 1) * STAGE_BYTES;
#pragma unroll
        for (int k16 = 0; k16 < 2; k16++) {
#pragma unroll
            for (int tap = 0; tap < 3; tap++) {
                uint32_t af[4][4];
#pragma unroll
                for (int m = 0; m < 4; m++)
                    ldm_x4(af[m], a_base + stg + (uint32_t)(tap*OT + m*16)*PITCH + k16*32);
                const uint32_t boff = stg + (uint32_t)Sx[tap]*PITCH + k16*32;
#pragma unroll
                for (int n = 0; n < 8; n++) {
                    uint32_t bf[2];
                    ldm_x2(bf, b_base + boff + (uint32_t)(n*8)*PITCH);
#pragma unroll
                    for (int m = 0; m < 4; m++)
                        mma16816(acc[m][n], af[m], bf);
                }
            }
        }
        __syncthreads();
        if (c + 2 < NCHUNK)
            stage_chunk(sbase + stg, Wq, Xt, o0, xrowbase, tid, (c + 2) * 64);
    }

    // ---- epilogue: stage y = s*acc + bias (leaky if mode 0) into smem [o][l] ----
    float* yt = (float*)smem;                 // reuses pipeline smem; pitch YPITCH
    const float s = g_scales[widx];
    const int g  = lane >> 2;
    const int tg = lane & 3;
#pragma unroll
    for (int m = 0; m < 4; m++) {
        const int r0 = o_w + m*16 + g;
        const float bv0 = bias[o0 + r0];
        const float bv8 = bias[o0 + r0 + 8];
#pragma unroll
        for (int n = 0; n < 8; n++) {
            const int col = l_w + n*8 + tg*2;
            float y0 = fmaf(s, acc[m][n][0], bv0);
            float y1 = fmaf(s, acc[m][n][1], bv0);
            float y2 = fmaf(s, acc[m][n][2], bv8);
            float y3 = fmaf(s, acc[m][n][3], bv8);
            if (mode == 0) {
                y0 = (y0 >= 0.f) ? y0 : 0.1f*y0;
                y1 = (y1 >= 0.f) ? y1 : 0.1f*y1;
                y2 = (y2 >= 0.f) ? y2 : 0.1f*y2;
                y3 = (y3 >= 0.f) ? y3 : 0.1f*y3;
            }
            yt[r0*YPITCH + col]         = y0;
            yt[r0*YPITCH + col + 1]     = y1;
            yt[(r0+8)*YPITCH + col]     = y2;
            yt[(r0+8)*YPITCH + col + 1] = y3;
        }
    }
    __syncthreads();

    if (mode == 1) {
        // residual add on fp32 x [b][c][l], coalesced over l; update yt in place
        for (int r = w; r < OT; r += 8) {
            float* rowp = xio + ((size_t)b*CC + o0 + r)*LL + l0;
#pragma unroll
            for (int i = 0; i < LT/32; i++) {
                int li = i*32 + lane;
                float xn = rowp[li] + yt[r*YPITCH + li];
                rowp[li] = xn;
                yt[r*YPITCH + li] = xn;
            }
        }
        __syncthreads();
    }

    // transposed fp16 store: [b][l][c], coalesced over c
    const size_t lrow0 = ((size_t)b*XL + XPAD + l0)*CC + o0;
    for (int li = w; li < LT; li += 8) {
        size_t off = lrow0 + (size_t)li*CC + lane;
#pragma unroll
        for (int k = 0; k < 4; k++) {
            float v = yt[(lane + 32*k)*YPITCH + li];
            out_t[off + 32*k] = __float2half_rn(v);
        }
    }
}

// ---------------- host ----------------
extern "C" void kernel_launch(void* const* d_in, const int* in_sizes, int n_in,
                              void* d_out, int out_size) {
    const float* x = (const float*)d_in[0];
    float* out = (float*)d_out;

    void *qp, *xp, *hp;
    cudaGetSymbolAddress(&qp, g_q);
    cudaGetSymbolAddress(&xp, g_xt);
    cudaGetSymbolAddress(&hp, g_ht);
    __half* qb = (__half*)qp;
    __half* xb = (__half*)xp;
    __half* hb = (__half*)hp;

    static int smem_set = 0;
    if (!smem_set) {
        cudaFuncSetAttribute(conv_mma_kernel, cudaFuncAttributeMaxDynamicSharedMemorySize, SMEM_TOTAL);
        smem_set = 1;
    }

    // Seed running x into d_out
    cudaMemcpyAsync(out, x, sizeof(float)*(size_t)BB*CC*LL, cudaMemcpyDeviceToDevice, 0);

    // Initial transpose of x -> fp16 [b][l][c]
    transpose_split_k<<<dim3(LL/64, CC/32, BB), 256>>>(x);

    // Quantize all 6 weight tensors (w at d_in 1,3,5,7,9,11)
    for (int t = 0; t < 6; t++) {
        const float* wt = (const float*)d_in[1 + 2*t];
        absmean_partial_k<<<256, 256>>>(wt);
        absmean_final_k<<<1, 256>>>(t);
        quantize_k<<<(WELEMS + 255)/256, 256>>>(wt, t);
    }

    dim3 grid(CC/OT, LL/LT, BB);   // (4, 32, 8) — o fastest so same-X blocks are adjacent
    const int dils[3] = {1, 3, 5};
    for (int br = 0; br < 3; br++) {
        const float* bA = (const float*)d_in[2 + 4*br];
        const float* bB = (const float*)d_in[4 + 4*br];
        // h = leakyrelu(convA_dilated(x)) -> ht
        conv_mma_kernel<<<grid, 256, SMEM_TOTAL>>>(
            qb + (size_t)(2*br)*3*CC*CC, xb, bA, out, hb, 2*br, dils[br], 0);
        // x += convB_dense(h); new x -> xt
        conv_mma_kernel<<<grid, 256, SMEM_TOTAL>>>(
            qb + (size_t)(2*br+1)*3*CC*CC, hb, bB, out, xb, 2*br+1, 1, 1);
    }
}

// round 17
// speedup vs baseline: 4.2372x; 1.0473x over previous
#include <cuda_runtime.h>
#include <cuda_fp16.h>
#include <math.h>
#include <stdint.h>

// ---------------- problem constants ----------------
#define BB 8
#define CC 512
#define LL 8192
#define KS 3
#define WELEMS (CC*CC*KS)

// ---------------- layout / tiling ----------------
#define XL 8448                 // padded rows per batch: 8 front pad + 8192 + tail pad (zeros)
#define XPAD 8
#define OT 128                  // block O tile
#define LT 256                  // block L tile
#define KC 32                   // ci per chunk
#define NCHUNK (CC/KC)          // 16
#define XROWS 266               // LT + 2*5 halo
#define PITCH 80                // smem row pitch bytes (64B data) -> conflict-free ldmatrix
#define W_OFF 0
#define W_BYTES (3*OT*PITCH)    // 30720
#define X_OFF W_BYTES
#define X_BYTES (XROWS*PITCH)   // 21280
#define STAGE_BYTES 52096       // aligned(W_BYTES + X_BYTES, 128)
#define NSEG_W (3*OT*4)         // 1536 16B segments
#define NSEG_X (XROWS*4)        // 1064
#define NSEG (NSEG_W + NSEG_X)  // 2600
#define YPITCH 261              // fp32 epilogue pitch (261%32=5 -> conflict-free cols)
#define SMEM_TOTAL (3*STAGE_BYTES)  // 156288 (>= OT*YPITCH*4 = 133632 for epilogue reuse)

// ---------------- device scratch (zero-initialized; pads stay zero) ----------------
__device__ __align__(1024) __half g_xt[(size_t)BB*XL*CC];       // x fp16 [b][l][c]
__device__ __align__(1024) __half g_ht[(size_t)BB*XL*CC];       // h fp16 [b][l][c]
__device__ __align__(1024) __half g_q[(size_t)18*CC*CC];        // ternary weights [widx*3+tap][o][ci]
__device__ float g_partial[6][256];
__device__ float g_scales[6];

// ---------------- asm helpers ----------------
__device__ __forceinline__ uint32_t smem_u32(const void* p) {
    uint32_t a;
    asm("{ .reg .u64 t; cvta.to.shared.u64 t, %1; cvt.u32.u64 %0, t; }" : "=r"(a) : "l"(p));
    return a;
}
__device__ __forceinline__ void cp16(uint32_t saddr, const void* gaddr) {
    asm volatile("cp.async.cg.shared.global [%0], [%1], 16;" :: "r"(saddr), "l"(gaddr));
}
__device__ __forceinline__ void cp_commit() { asm volatile("cp.async.commit_group;"); }
template<int N> __device__ __forceinline__ void cp_wait() {
    asm volatile("cp.async.wait_group %0;" :: "n"(N));
}
__device__ __forceinline__ void ldm_x4(uint32_t* r, uint32_t addr) {
    asm volatile("ldmatrix.sync.aligned.m8n8.x4.shared.b16 {%0,%1,%2,%3}, [%4];"
                 : "=r"(r[0]), "=r"(r[1]), "=r"(r[2]), "=r"(r[3]) : "r"(addr));
}
__device__ __forceinline__ void ldm_x2(uint32_t* r, uint32_t addr) {
    asm volatile("ldmatrix.sync.aligned.m8n8.x2.shared.b16 {%0,%1}, [%2];"
                 : "=r"(r[0]), "=r"(r[1]) : "r"(addr));
}
__device__ __forceinline__ void mma16816(float* d, const uint32_t* a, const uint32_t* b) {
    asm volatile("mma.sync.aligned.m16n8k16.row.col.f32.f16.f16.f32 "
                 "{%0,%1,%2,%3}, {%4,%5,%6,%7}, {%8,%9}, {%0,%1,%2,%3};"
                 : "+f"(d[0]), "+f"(d[1]), "+f"(d[2]), "+f"(d[3])
                 : "r"(a[0]), "r"(a[1]), "r"(a[2]), "r"(a[3]), "r"(b[0]), "r"(b[1]));
}

// ---------------- batched weight quantization (3 launches total) ----------------
__global__ void absmean_partial_all_k(const float* w0, const float* w1, const float* w2,
                                      const float* w3, const float* w4, const float* w5) {
    const float* ws[6] = {w0, w1, w2, w3, w4, w5};
    const float* w = ws[blockIdx.y];
    __shared__ float red[256];
    float s = 0.f;
    for (int i = blockIdx.x*256 + threadIdx.x; i < WELEMS; i += 256*256) s += fabsf(w[i]);
    red[threadIdx.x] = s;
    __syncthreads();
    for (int st = 128; st > 0; st >>= 1) {
        if (threadIdx.x < st) red[threadIdx.x] += red[threadIdx.x + st];
        __syncthreads();
    }
    if (threadIdx.x == 0) g_partial[blockIdx.y][blockIdx.x] = red[0];
}
__global__ void absmean_final_all_k() {
    __shared__ float red[256];
    red[threadIdx.x] = g_partial[blockIdx.x][threadIdx.x];
    __syncthreads();
    for (int st = 128; st > 0; st >>= 1) {
        if (threadIdx.x < st) red[threadIdx.x] += red[threadIdx.x + st];
        __syncthreads();
    }
    if (threadIdx.x == 0) g_scales[blockIdx.x] = red[0] / (float)WELEMS + 1e-5f;
}
// w [o][i][k] -> g_q[(t*3+k)][o][i] ternary fp16 (exact; scale applied in epilogue)
__global__ void quantize_all_k(const float* w0, const float* w1, const float* w2,
                               const float* w3, const float* w4, const float* w5) {
    const float* ws[6] = {w0, w1, w2, w3, w4, w5};
    int t = blockIdx.x / 3072;                  // 3072 blocks per tensor
    int idx = (blockIdx.x - t*3072)*256 + threadIdx.x;
    if (idx >= WELEMS) return;
    const float* w = ws[t];
    float s = g_scales[t];
    int k = idx % KS;
    int i = (idx / KS) % CC;
    int o = idx / (KS*CC);
    float q = rintf(w[idx] / s);
    q = fminf(1.f, fmaxf(-1.f, q));
    g_q[(((size_t)t*3 + k)*CC + o)*CC + i] = __float2half_rn(q);
}

// ---------------- initial transpose: fp32 [b][c][l] -> fp16 [b][l][c] ----------------
__global__ void transpose_split_k(const float* __restrict__ src) {
    __shared__ float t[32][65];
    int b = blockIdx.z, c0 = blockIdx.y*32, l0 = blockIdx.x*64;
#pragma unroll
    for (int k = 0; k < 8; k++) {
        int idx = threadIdx.x + k*256;
        int cl = idx >> 6, ll_ = idx & 63;
        t[cl][ll_] = src[((size_t)b*CC + c0 + cl)*LL + l0 + ll_];
    }
    __syncthreads();
#pragma unroll
    for (int k = 0; k < 8; k++) {
        int idx = threadIdx.x + k*256;
        int ll_ = idx >> 5, cl = idx & 31;
        g_xt[((size_t)b*XL + XPAD + l0 + ll_)*CC + c0 + cl] = __float2half_rn(t[cl][ll_]);
    }
}

// ---------------- staging: one chunk's W+X -> smem stage ----------------
__device__ __forceinline__ void stage_chunk(uint32_t sdst, const __half* Wq, const __half* Xt,
                                            int o0, size_t xrowbase, int tid, int adv) {
    for (int s = tid; s < NSEG; s += 256) {
        uint32_t so; const char* g;
        if (s < NSEG_W) {
            int row = s >> 2, sg = s & 3;           // row in [0,384)
            int tap = row >> 7, rr = row & 127;     // OT=128 -> shifts
            so = W_OFF + (uint32_t)row*PITCH + sg*16;
            g = (const char*)(Wq + ((size_t)tap*CC + o0 + rr)*CC) + sg*16 + adv;
        } else {
            int t2 = s - NSEG_W;
            int row = t2 >> 2, sg = t2 & 3;
            so = X_OFF + (uint32_t)row*PITCH + sg*16;
            g = (const char*)(Xt + (xrowbase + row)*CC) + sg*16 + adv;
        }
        cp16(sdst + so, g);
    }
    cp_commit();
}

// ---------------- fused conv kernel (fp16 mma.sync implicit GEMM) ----------------
// block tile 128(O) x 256(L); 8 warps as 2(O) x 4(L); warp tile 64x64 (m=4, n=8)
// 3-stage cp.async ring, ONE __syncthreads per chunk:
//   stage written at iter c ((c+2)%3) was read at iter c-1; the top-of-loop barrier
//   orders those reads before these writes.
// mode 0: out = leakyrelu(s*D + bias) -> fp16 [b][l][c]
// mode 1: xio += s*D + bias (fp32 [b][c][l]); new x -> fp16 [b][l][c]
__global__ void __launch_bounds__(256, 1)
conv_mma_kernel(const __half* __restrict__ Wq,   // [3][512][512] for this layer
                const __half* __restrict__ Xt,   // [b][XL][512]
                const float* __restrict__ bias,
                float* __restrict__ xio,
                __half* __restrict__ out_t,
                int widx, int dil, int mode)
{
    extern __shared__ char smem[];
    const uint32_t sbase = smem_u32(smem);

    const int tid  = threadIdx.x;
    const int lane = tid & 31;
    const int w    = tid >> 5;
    const int o_w  = (w >> 2) * 64;     // warp O offset (0/64)
    const int l_w  = (w & 3) * 64;      // warp L offset (0..192)
    const int o0   = blockIdx.x * OT;
    const int l0   = blockIdx.y * LT;
    const int b    = blockIdx.z;
    const size_t xrowbase = (size_t)b*XL + XPAD + l0 - 5;

    // ---- ldmatrix base addresses ----
    const uint32_t a_base = sbase + W_OFF
                  + (uint32_t)(o_w + (lane & 7) + ((lane >> 3) & 1)*8)*PITCH
                  + (lane >> 4)*16;
    const uint32_t b_base = sbase + X_OFF
                  + (uint32_t)(l_w + (lane & 7))*PITCH
                  + ((lane >> 3) & 1)*16;

    float acc[4][8][4];
#pragma unroll
    for (int m = 0; m < 4; m++)
#pragma unroll
        for (int n = 0; n < 8; n++)
#pragma unroll
            for (int e = 0; e < 4; e++) acc[m][n][e] = 0.f;

    const int Sx[3] = {5 - dil, 5, 5 + dil};

    // ---- prologue: issue chunks 0 and 1 into stages 0 and 1 ----
    stage_chunk(sbase,               Wq, Xt, o0, xrowbase, tid, 0);
    stage_chunk(sbase + STAGE_BYTES, Wq, Xt, o0, xrowbase, tid, 64);

    for (int c = 0; c < NCHUNK; c++) {
        if (c < NCHUNK - 1) cp_wait<1>(); else cp_wait<0>();
        __syncthreads();
        const uint32_t stg = (uint32_t)(c % 3) * STAGE_BYTES;
#pragma unroll
        for (int k16 = 0; k16 < 2; k16++) {
#pragma unroll
            for (int tap = 0; tap < 3; tap++) {
                uint32_t af[4][4];
#pragma unroll
                for (int m = 0; m < 4; m++)
                    ldm_x4(af[m], a_base + stg + (uint32_t)(tap*OT + m*16)*PITCH + k16*32);
                const uint32_t boff = stg + (uint32_t)Sx[tap]*PITCH + k16*32;
#pragma unroll
                for (int n = 0; n < 8; n++) {
                    uint32_t bf[2];
                    ldm_x2(bf, b_base + boff + (uint32_t)(n*8)*PITCH);
#pragma unroll
                    for (int m = 0; m < 4; m++)
                        mma16816(acc[m][n], af[m], bf);
                }
            }
        }
        if (c + 2 < NCHUNK)
            stage_chunk(sbase + (uint32_t)((c + 2) % 3)*STAGE_BYTES,
                        Wq, Xt, o0, xrowbase, tid, (c + 2) * 64);
    }
    __syncthreads();   // all warps done reading stages before yt overwrites smem

    // ---- epilogue: stage y = s*acc + bias (leaky if mode 0) into smem [o][l] ----
    float* yt = (float*)smem;                 // reuses pipeline smem; pitch YPITCH
    const float s = g_scales[widx];
    const int g  = lane >> 2;
    const int tg = lane & 3;
#pragma unroll
    for (int m = 0; m < 4; m++) {
        const int r0 = o_w + m*16 + g;
        const float bv0 = bias[o0 + r0];
        const float bv8 = bias[o0 + r0 + 8];
#pragma unroll
        for (int n = 0; n < 8; n++) {
            const int col = l_w + n*8 + tg*2;
            float y0 = fmaf(s, acc[m][n][0], bv0);
            float y1 = fmaf(s, acc[m][n][1], bv0);
            float y2 = fmaf(s, acc[m][n][2], bv8);
            float y3 = fmaf(s, acc[m][n][3], bv8);
            if (mode == 0) {
                y0 = (y0 >= 0.f) ? y0 : 0.1f*y0;
                y1 = (y1 >= 0.f) ? y1 : 0.1f*y1;
                y2 = (y2 >= 0.f) ? y2 : 0.1f*y2;
                y3 = (y3 >= 0.f) ? y3 : 0.1f*y3;
            }
            yt[r0*YPITCH + col]         = y0;
            yt[r0*YPITCH + col + 1]     = y1;
            yt[(r0+8)*YPITCH + col]     = y2;
            yt[(r0+8)*YPITCH + col + 1] = y3;
        }
    }
    __syncthreads();

    if (mode == 1) {
        // residual add on fp32 x [b][c][l], coalesced over l; update yt in place
        for (int r = w; r < OT; r += 8) {
            float* rowp = xio + ((size_t)b*CC + o0 + r)*LL + l0;
#pragma unroll
            for (int i = 0; i < LT/32; i++) {
                int li = i*32 + lane;
                float xn = rowp[li] + yt[r*YPITCH + li];
                rowp[li] = xn;
                yt[r*YPITCH + li] = xn;
            }
        }
        __syncthreads();
    }

    // transposed fp16 store: [b][l][c], coalesced over c
    const size_t lrow0 = ((size_t)b*XL + XPAD + l0)*CC + o0;
    for (int li = w; li < LT; li += 8) {
        size_t off = lrow0 + (size_t)li*CC + lane;
#pragma unroll
        for (int k = 0; k < 4; k++) {
            float v = yt[(lane + 32*k)*YPITCH + li];
            out_t[off + 32*k] = __float2half_rn(v);
        }
    }
}

// ---------------- host ----------------
extern "C" void kernel_launch(void* const* d_in, const int* in_sizes, int n_in,
                              void* d_out, int out_size) {
    const float* x = (const float*)d_in[0];
    float* out = (float*)d_out;

    void *qp, *xp, *hp;
    cudaGetSymbolAddress(&qp, g_q);
    cudaGetSymbolAddress(&xp, g_xt);
    cudaGetSymbolAddress(&hp, g_ht);
    __half* qb = (__half*)qp;
    __half* xb = (__half*)xp;
    __half* hb = (__half*)hp;

    static int smem_set = 0;
    if (!smem_set) {
        cudaFuncSetAttribute(conv_mma_kernel, cudaFuncAttributeMaxDynamicSharedMemorySize, SMEM_TOTAL);
        smem_set = 1;
    }

    // Seed running x into d_out
    cudaMemcpyAsync(out, x, sizeof(float)*(size_t)BB*CC*LL, cudaMemcpyDeviceToDevice, 0);

    // Initial transpose of x -> fp16 [b][l][c]
    transpose_split_k<<<dim3(LL/64, CC/32, BB), 256>>>(x);

    // Quantize all 6 weight tensors in 3 launches (w at d_in 1,3,5,7,9,11)
    const float* w0 = (const float*)d_in[1];
    const float* w1 = (const float*)d_in[3];
    const float* w2 = (const float*)d_in[5];
    const float* w3 = (const float*)d_in[7];
    const float* w4 = (const float*)d_in[9];
    const float* w5 = (const float*)d_in[11];
    absmean_partial_all_k<<<dim3(256, 6), 256>>>(w0, w1, w2, w3, w4, w5);
    absmean_final_all_k<<<6, 256>>>();
    quantize_all_k<<<6*3072, 256>>>(w0, w1, w2, w3, w4, w5);

    dim3 grid(CC/OT, LL/LT, BB);   // (4, 32, 8) — o fastest so same-X blocks are adjacent
    const int dils[3] = {1, 3, 5};
    for (int br = 0; br < 3; br++) {
        const float* bA = (const float*)d_in[2 + 4*br];
        const float* bB = (const float*)d_in[4 + 4*br];
        // h = leakyrelu(convA_dilated(x)) -> ht
        conv_mma_kernel<<<grid, 256, SMEM_TOTAL>>>(
            qb + (size_t)(2*br)*3*CC*CC, xb, bA, out, hb, 2*br, dils[br], 0);
        // x += convB_dense(h); new x -> xt
        conv_mma_kernel<<<grid, 256, SMEM_TOTAL>>>(
            qb + (size_t)(2*br+1)*3*CC*CC, hb, bB, out, xb, 2*br+1, 1, 1);
    }
}